// round 16
// baseline (speedup 1.0000x reference)
#include <cuda_runtime.h>
#include <cstdint>

// ---------------- config ----------------
#define CTAS        1024
#define THREADS     256              // 8 warps, each fully independent
#define UNIT_ROWS   32
#define UNIT_BYTES  8192
#define NSLOTS      3
#define NUNITS      4                // 8 warps * 4 * 32 rows * 1024 CTAs = 2^20
#define ROWS_CTA    1024

// smem: FB (fragment-major tf32 W, 16 KB) + per-warp 3-slot rings
#define FB_BYTES    16384
#define SMEM_X      FB_BYTES
#define SMEM_TOTAL  (FB_BYTES + 8 * NSLOTS * UNIT_BYTES)   // 212992 -> 1 CTA/SM

// ---------------- math constants ----------------
#define C_SCALE_L2E  4.3280851227f   // 3 * log2(e)
#define C_CLAMP_L2E 14.4269504089f   // 10 * log2(e)
#define C_LN2        0.6931471806f

// ---------------- helpers ----------------
static __device__ __forceinline__ uint32_t smem_u32(const void* p) {
    uint32_t a;
    asm("{ .reg .u64 t; cvta.to.shared.u64 t, %1; cvt.u32.u64 %0, t; }"
        : "=r"(a) : "l"(p));
    return a;
}
static __device__ __forceinline__ void cp16(uint32_t s, const void* g) {
    asm volatile("cp.async.cg.shared.global [%0], [%1], 16;" :: "r"(s), "l"(g));
}
#define CP_COMMIT() asm volatile("cp.async.commit_group;" ::: "memory")
#define CP_WAIT2()  asm volatile("cp.async.wait_group 2;" ::: "memory")

static __device__ __forceinline__ float exp2_fast(float x) {
    float r; asm("ex2.approx.ftz.f32 %0, %1;" : "=f"(r) : "f"(x)); return r;
}
static __device__ __forceinline__ float lg2_fast(float x) {
    float r; asm("lg2.approx.f32 %0, %1;" : "=f"(r) : "f"(x)); return r;
}
static __device__ __forceinline__ float rcp_fast(float x) {
    float r; asm("rcp.approx.ftz.f32 %0, %1;" : "=f"(r) : "f"(x)); return r;
}
static __device__ __forceinline__ uint32_t f2tf32(float v) {
    uint32_t r; asm("cvt.rna.tf32.f32 %0, %1;" : "=r"(r) : "f"(v)); return r;
}

// mma.sync m16n8k8 tf32
static __device__ __forceinline__ void mma_tf32(
    float* d, uint32_t a0, uint32_t a1, uint32_t a2, uint32_t a3,
    uint32_t b0, uint32_t b1) {
    asm volatile(
        "mma.sync.aligned.m16n8k8.row.col.f32.tf32.tf32.f32 "
        "{%0,%1,%2,%3}, {%4,%5,%6,%7}, {%8,%9}, {%0,%1,%2,%3};"
        : "+f"(d[0]), "+f"(d[1]), "+f"(d[2]), "+f"(d[3])
        : "r"(a0), "r"(a1), "r"(a2), "r"(a3), "r"(b0), "r"(b1));
}

static __device__ __forceinline__ float expv(float z) {
    float w = fminf(fmaxf(z * C_SCALE_L2E, -C_CLAMP_L2E), C_CLAMP_L2E);
    return exp2_fast(w);
}
// mish(ln s): e^(ln s) == s exactly -> tanh(softplus) = ((1+s)^2-1)/((1+s)^2+1)
static __device__ __forceinline__ float mish_of_ln(float s) {
    float lse = C_LN2 * lg2_fast(s);
    float up  = s + 1.0f;
    float q   = up * up;
    return lse * (q - 1.0f) * rcp_fast(q + 1.0f);
}

// load one 32-row unit (8 KB contiguous in gmem)
// dst swizzle: 16B-chunk c -> c ^ ((row&3)<<2)   (R7-verified; LDS.128-compatible)
static __device__ __forceinline__ void load_unit(
    uint32_t dst_base, const float* __restrict__ src, int lane) {
#pragma unroll
    for (int i = 0; i < 16; i++) {
        int idx = i * 32 + lane;            // 512 16B-chunks
        int r = idx >> 4, c = idx & 15;
        cp16(dst_base + (uint32_t)(r * 256 + ((c ^ ((r & 3) << 2)) << 4)),
             src + (size_t)idx * 4);
    }
}

// ---------------- kernel ----------------
__global__ void __launch_bounds__(THREADS, 1) fused_lin_lse_mish(
    const float* __restrict__ x, const float* __restrict__ W,
    float* __restrict__ out) {
    extern __shared__ char smem[];
    const uint32_t sb = smem_u32(smem);
    const int tid  = threadIdx.x;
    const int lane = tid & 31;
    const int w    = tid >> 5;
    const int g    = lane >> 2;          // 0..7
    const int t    = lane & 3;           // 0..3

    const size_t wrow0 = (size_t)blockIdx.x * ROWS_CTA
                       + (size_t)w * (NUNITS * UNIT_ROWS);
    const uint32_t ring = sb + SMEM_X + (uint32_t)w * (NSLOTS * UNIT_BYTES);

    // ---- prologue: fill all 3 slots (DRAM starts immediately) ----
#pragma unroll
    for (int s = 0; s < NSLOTS; s++) {
        load_unit(ring + (uint32_t)s * UNIT_BYTES,
                  x + (wrow0 + (size_t)s * UNIT_ROWS) * 64, lane);
        CP_COMMIT();
    }

    // ---- build fragment-major W (FB) for PERMUTED-K mapping ----
    // mma kb = 2*seg+m uses k-slot t -> col 16seg+4t+2m, slot t+4 -> col+1.
    // entry e=(kb*4+j)*32+lane holds {W[n0][col],W[n0][col+1],W[n1][col],W[n1][col+1]},
    // n0 = 16j+eg, n1 = n0+8 (nb = 2j, 2j+1).
#pragma unroll
    for (int i = 0; i < 4; i++) {
        int e  = i * THREADS + tid;       // 1024 entries
        int el = e & 31, j = (e >> 5) & 3, kb = e >> 7;
        int eg = el >> 2, et = el & 3;
        int n0 = 16 * j + eg, n1 = n0 + 8;
        int col = 16 * (kb >> 1) + 4 * et + 2 * (kb & 1);
        uint4 v;
        v.x = f2tf32(W[n0 * 64 + col]);
        v.y = f2tf32(W[n0 * 64 + col + 1]);
        v.z = f2tf32(W[n1 * 64 + col]);
        v.w = f2tf32(W[n1 * 64 + col + 1]);
        *reinterpret_cast<uint4*>(smem + e * 16) = v;
    }
    __syncthreads();                      // only block-wide sync in the kernel

    const uint32_t cxor = (uint32_t)((g & 3) << 2);   // same for rows g,g+8,g+16,g+24

#pragma unroll
    for (int u = 0; u < NUNITS; u++) {
        CP_WAIT2();                       // unit u resident (this warp's own loads)

        const char* As = smem + SMEM_X + (size_t)w * (NSLOTS * UNIT_BYTES)
                       + (size_t)(u % NSLOTS) * UNIT_BYTES;

        float acc[2][8][4];
#pragma unroll
        for (int mt = 0; mt < 2; mt++)
#pragma unroll
            for (int nb = 0; nb < 8; nb++)
#pragma unroll
                for (int q = 0; q < 4; q++) acc[mt][nb][q] = 0.0f;

#pragma unroll
        for (int seg = 0; seg < 4; seg++) {
            // A: 4 rows x one LDS.128 each (cols 16seg+4t .. +3, permuted-K)
            const uint32_t ch = (uint32_t)(((4 * seg + t) ^ cxor) << 4);
            uint4 v0 = *reinterpret_cast<const uint4*>(As + (g)      * 256 + ch);
            uint4 v1 = *reinterpret_cast<const uint4*>(As + (g + 8)  * 256 + ch);
            uint4 v2 = *reinterpret_cast<const uint4*>(As + (g + 16) * 256 + ch);
            uint4 v3 = *reinterpret_cast<const uint4*>(As + (g + 24) * 256 + ch);

#pragma unroll
            for (int m = 0; m < 2; m++) {
                const int kb = 2 * seg + m;
                // B fragments: 4x LDS.128 from FB
                uint32_t b[8][2];
#pragma unroll
                for (int j = 0; j < 4; j++) {
                    uint4 bv = *reinterpret_cast<const uint4*>(
                        smem + ((kb * 4 + j) * 32 + lane) * 16);
                    b[2 * j][0]     = bv.x;
                    b[2 * j][1]     = bv.y;
                    b[2 * j + 1][0] = bv.z;
                    b[2 * j + 1][1] = bv.w;
                }
                // raw fp32 bits feed mma.tf32 directly (R13-proven). NO conversion:
                // m=0 -> cols (+0,+1) = (.x,.y) ; m=1 -> (+2,+3) = (.z,.w)
                uint32_t a00 = m ? v0.z : v0.x;
                uint32_t a01 = m ? v1.z : v1.x;
                uint32_t a02 = m ? v0.w : v0.y;
                uint32_t a03 = m ? v1.w : v1.y;
                uint32_t a10 = m ? v2.z : v2.x;
                uint32_t a11 = m ? v3.z : v3.x;
                uint32_t a12 = m ? v2.w : v2.y;
                uint32_t a13 = m ? v3.w : v3.y;
#pragma unroll
                for (int nb = 0; nb < 8; nb++) {
                    mma_tf32(acc[0][nb], a00, a01, a02, a03, b[nb][0], b[nb][1]);
                    mma_tf32(acc[1][nb], a10, a11, a12, a13, b[nb][0], b[nb][1]);
                }
            }
        }

        // ---- refill the slot just consumed BEFORE epilogue (overlap DRAM) ----
        if (u + NSLOTS < NUNITS)
            load_unit(ring + (uint32_t)(u % NSLOTS) * UNIT_BYTES,
                      x + (wrow0 + (size_t)(u + NSLOTS) * UNIT_ROWS) * 64, lane);
        CP_COMMIT();                      // uniform group accounting (empty ok)

        // ---- epilogue: full 64-col row sums, fully in-warp ----
#pragma unroll
        for (int mt = 0; mt < 2; mt++) {
            float sl = 0.0f, sh = 0.0f;
#pragma unroll
            for (int nb = 0; nb < 8; nb++) {
                sl += expv(acc[mt][nb][0]) + expv(acc[mt][nb][1]);
                sh += expv(acc[mt][nb][2]) + expv(acc[mt][nb][3]);
            }
            sl += __shfl_xor_sync(0xFFFFFFFF, sl, 1);
            sl += __shfl_xor_sync(0xFFFFFFFF, sl, 2);
            sh += __shfl_xor_sync(0xFFFFFFFF, sh, 1);
            sh += __shfl_xor_sync(0xFFFFFFFF, sh, 2);
            if (t == 0) {
                size_t row = wrow0 + (size_t)u * UNIT_ROWS + mt * 16 + g;
                out[row]     = mish_of_ln(sl);
                out[row + 8] = mish_of_ln(sh);
            }
        }
    }
}

// ---------------- launch ----------------
extern "C" void kernel_launch(void* const* d_in, const int* in_sizes, int n_in,
                              void* d_out, int out_size) {
    (void)in_sizes; (void)n_in; (void)out_size;
    const float* x = (const float*)d_in[0];
    const float* W = (const float*)d_in[1];
    float* out = (float*)d_out;

    cudaFuncSetAttribute(fused_lin_lse_mish,
                         cudaFuncAttributeMaxDynamicSharedMemorySize, SMEM_TOTAL);
    fused_lin_lse_mish<<<CTAS, THREADS, SMEM_TOTAL>>>(x, W, out);
}

// round 17
// speedup vs baseline: 1.0024x; 1.0024x over previous
#include <cuda_runtime.h>
#include <cstdint>

// ---------------- config ----------------
#define CTAS        1024
#define THREADS     256              // 8 warps, each fully independent
#define UNIT_ROWS   32
#define UNIT_BYTES  8192
#define NSLOTS      3
#define NUNITS      4                // 8 warps * 4 * 32 rows * 1024 CTAs = 2^20
#define ROWS_CTA    1024

// smem: FB (fragment-major tf32 W, 16 KB) + per-warp 3-slot rings
#define FB_BYTES    16384
#define SMEM_X      FB_BYTES
#define SMEM_TOTAL  (FB_BYTES + 8 * NSLOTS * UNIT_BYTES)   // 212992 -> 1 CTA/SM

// ---------------- math constants ----------------
#define C_SCALE_L2E  4.3280851227f   // 3 * log2(e)
#define C_CLAMP_L2E 14.4269504089f   // 10 * log2(e)
#define C_LN2        0.6931471806f

// ---------------- helpers ----------------
static __device__ __forceinline__ uint32_t smem_u32(const void* p) {
    uint32_t a;
    asm("{ .reg .u64 t; cvta.to.shared.u64 t, %1; cvt.u32.u64 %0, t; }"
        : "=r"(a) : "l"(p));
    return a;
}
static __device__ __forceinline__ void cp16(uint32_t s, const void* g) {
    asm volatile("cp.async.cg.shared.global [%0], [%1], 16;" :: "r"(s), "l"(g));
}
#define CP_COMMIT() asm volatile("cp.async.commit_group;" ::: "memory")
#define CP_WAIT2()  asm volatile("cp.async.wait_group 2;" ::: "memory")

static __device__ __forceinline__ float exp2_fast(float x) {
    float r; asm("ex2.approx.ftz.f32 %0, %1;" : "=f"(r) : "f"(x)); return r;
}
static __device__ __forceinline__ float lg2_fast(float x) {
    float r; asm("lg2.approx.f32 %0, %1;" : "=f"(r) : "f"(x)); return r;
}
static __device__ __forceinline__ float rcp_fast(float x) {
    float r; asm("rcp.approx.ftz.f32 %0, %1;" : "=f"(r) : "f"(x)); return r;
}
static __device__ __forceinline__ uint32_t f2tf32(float v) {
    uint32_t r; asm("cvt.rna.tf32.f32 %0, %1;" : "=r"(r) : "f"(v)); return r;
}

// mma.sync m16n8k8 tf32
static __device__ __forceinline__ void mma_tf32(
    float* d, uint32_t a0, uint32_t a1, uint32_t a2, uint32_t a3,
    uint32_t b0, uint32_t b1) {
    asm volatile(
        "mma.sync.aligned.m16n8k8.row.col.f32.tf32.tf32.f32 "
        "{%0,%1,%2,%3}, {%4,%5,%6,%7}, {%8,%9}, {%0,%1,%2,%3};"
        : "+f"(d[0]), "+f"(d[1]), "+f"(d[2]), "+f"(d[3])
        : "r"(a0), "r"(a1), "r"(a2), "r"(a3), "r"(b0), "r"(b1));
}

static __device__ __forceinline__ float expv(float z) {
    float w = fminf(fmaxf(z * C_SCALE_L2E, -C_CLAMP_L2E), C_CLAMP_L2E);
    return exp2_fast(w);
}
// mish(ln s): e^(ln s) == s exactly -> tanh(softplus) = ((1+s)^2-1)/((1+s)^2+1)
static __device__ __forceinline__ float mish_of_ln(float s) {
    float lse = C_LN2 * lg2_fast(s);
    float up  = s + 1.0f;
    float q   = up * up;
    return lse * (q - 1.0f) * rcp_fast(q + 1.0f);
}

// load one 32-row unit (8 KB contiguous in gmem)
// dst swizzle: 16B-chunk c -> c ^ ((row&3)<<2)   (R16-verified; LDS.128-compatible)
static __device__ __forceinline__ void load_unit(
    uint32_t dst_base, const float* __restrict__ src, int lane) {
#pragma unroll
    for (int i = 0; i < 16; i++) {
        int idx = i * 32 + lane;            // 512 16B-chunks
        int r = idx >> 4, c = idx & 15;
        cp16(dst_base + (uint32_t)(r * 256 + ((c ^ ((r & 3) << 2)) << 4)),
             src + (size_t)idx * 4);
    }
}

// ---------------- kernel ----------------
__global__ void __launch_bounds__(THREADS, 1) fused_lin_lse_mish(
    const float* __restrict__ x, const float* __restrict__ W,
    float* __restrict__ out) {
    extern __shared__ char smem[];
    const uint32_t sb = smem_u32(smem);
    const int tid  = threadIdx.x;
    const int lane = tid & 31;
    const int w    = tid >> 5;
    const int g    = lane >> 2;          // 0..7
    const int t    = lane & 3;           // 0..3

    const size_t wrow0 = (size_t)blockIdx.x * ROWS_CTA
                       + (size_t)w * (NUNITS * UNIT_ROWS);
    const uint32_t ring = sb + SMEM_X + (uint32_t)w * (NSLOTS * UNIT_BYTES);

    // ---- prologue: fill all 3 slots (DRAM starts immediately) ----
#pragma unroll
    for (int s = 0; s < NSLOTS; s++) {
        load_unit(ring + (uint32_t)s * UNIT_BYTES,
                  x + (wrow0 + (size_t)s * UNIT_ROWS) * 64, lane);
        CP_COMMIT();
    }

    // ---- build fragment-major W (FB) for PERMUTED-K mapping (R16-verified) ----
    // mma kb = 2*seg+m uses k-slot t -> col 16seg+4t+2m, slot t+4 -> col+1.
#pragma unroll
    for (int i = 0; i < 4; i++) {
        int e  = i * THREADS + tid;       // 1024 entries
        int el = e & 31, j = (e >> 5) & 3, kb = e >> 7;
        int eg = el >> 2, et = el & 3;
        int n0 = 16 * j + eg, n1 = n0 + 8;
        int col = 16 * (kb >> 1) + 4 * et + 2 * (kb & 1);
        uint4 v;
        v.x = f2tf32(W[n0 * 64 + col]);
        v.y = f2tf32(W[n0 * 64 + col + 1]);
        v.z = f2tf32(W[n1 * 64 + col]);
        v.w = f2tf32(W[n1 * 64 + col + 1]);
        *reinterpret_cast<uint4*>(smem + e * 16) = v;
    }
    __syncthreads();                      // only block-wide sync in the kernel

    const uint32_t cxor = (uint32_t)((g & 3) << 2);   // same for rows g+0/8/16/24

#pragma unroll
    for (int u = 0; u < NUNITS; u++) {
        CP_WAIT2();                       // unit u resident (this warp's own loads)

        const char* As = smem + SMEM_X + (size_t)w * (NSLOTS * UNIT_BYTES)
                       + (size_t)(u % NSLOTS) * UNIT_BYTES;

        float acc[2][8][4];
#pragma unroll
        for (int mt = 0; mt < 2; mt++)
#pragma unroll
            for (int nb = 0; nb < 8; nb++)
#pragma unroll
                for (int q = 0; q < 4; q++) acc[mt][nb][q] = 0.0f;

#pragma unroll
        for (int seg = 0; seg < 4; seg++) {
            // A: 4 rows x one LDS.128 each (logical cols 16seg+4t .. +3)
            const uint32_t ch = (uint32_t)(((4 * seg + t) ^ cxor) << 4);
            uint4 v0 = *reinterpret_cast<const uint4*>(As + (g)      * 256 + ch);
            uint4 v1 = *reinterpret_cast<const uint4*>(As + (g + 8)  * 256 + ch);
            uint4 v2 = *reinterpret_cast<const uint4*>(As + (g + 16) * 256 + ch);
            uint4 v3 = *reinterpret_cast<const uint4*>(As + (g + 24) * 256 + ch);

            // ---- kb = 2*seg (m=0): A slots = cols (+0,+1) = (.x,.y) ----
            {
                const int kb = 2 * seg;
                uint32_t b0[8], b1[8];
#pragma unroll
                for (int j = 0; j < 4; j++) {
                    uint4 bv = *reinterpret_cast<const uint4*>(
                        smem + ((kb * 4 + j) * 32 + lane) * 16);
                    b0[2 * j]     = bv.x;  b1[2 * j]     = bv.y;
                    b0[2 * j + 1] = bv.z;  b1[2 * j + 1] = bv.w;
                }
#pragma unroll
                for (int nb = 0; nb < 8; nb++) {
                    mma_tf32(acc[0][nb], v0.x, v1.x, v0.y, v1.y, b0[nb], b1[nb]);
                    mma_tf32(acc[1][nb], v2.x, v3.x, v2.y, v3.y, b0[nb], b1[nb]);
                }
            }
            // ---- kb = 2*seg+1 (m=1): A slots = cols (+2,+3) = (.z,.w) ----
            {
                const int kb = 2 * seg + 1;
                uint32_t b0[8], b1[8];
#pragma unroll
                for (int j = 0; j < 4; j++) {
                    uint4 bv = *reinterpret_cast<const uint4*>(
                        smem + ((kb * 4 + j) * 32 + lane) * 16);
                    b0[2 * j]     = bv.x;  b1[2 * j]     = bv.y;
                    b0[2 * j + 1] = bv.z;  b1[2 * j + 1] = bv.w;
                }
#pragma unroll
                for (int nb = 0; nb < 8; nb++) {
                    mma_tf32(acc[0][nb], v0.z, v1.z, v0.w, v1.w, b0[nb], b1[nb]);
                    mma_tf32(acc[1][nb], v2.z, v3.z, v2.w, v3.w, b0[nb], b1[nb]);
                }
            }
        }

        // ---- refill the slot just consumed BEFORE epilogue (overlap DRAM) ----
        if (u + NSLOTS < NUNITS)
            load_unit(ring + (uint32_t)(u % NSLOTS) * UNIT_BYTES,
                      x + (wrow0 + (size_t)(u + NSLOTS) * UNIT_ROWS) * 64, lane);
        CP_COMMIT();                      // uniform group accounting (empty ok)

        // ---- epilogue: full 64-col row sums, fully in-warp ----
#pragma unroll
        for (int mt = 0; mt < 2; mt++) {
            float sl = 0.0f, sh = 0.0f;
#pragma unroll
            for (int nb = 0; nb < 8; nb++) {
                sl += expv(acc[mt][nb][0]) + expv(acc[mt][nb][1]);
                sh += expv(acc[mt][nb][2]) + expv(acc[mt][nb][3]);
            }
            sl += __shfl_xor_sync(0xFFFFFFFF, sl, 1);
            sl += __shfl_xor_sync(0xFFFFFFFF, sl, 2);
            sh += __shfl_xor_sync(0xFFFFFFFF, sh, 1);
            sh += __shfl_xor_sync(0xFFFFFFFF, sh, 2);
            if (t == 0) {
                size_t row = wrow0 + (size_t)u * UNIT_ROWS + mt * 16 + g;
                out[row]     = mish_of_ln(sl);
                out[row + 8] = mish_of_ln(sh);
            }
        }
    }
}

// ---------------- launch ----------------
extern "C" void kernel_launch(void* const* d_in, const int* in_sizes, int n_in,
                              void* d_out, int out_size) {
    (void)in_sizes; (void)n_in; (void)out_size;
    const float* x = (const float*)d_in[0];
    const float* W = (const float*)d_in[1];
    float* out = (float*)d_out;

    cudaFuncSetAttribute(fused_lin_lse_mish,
                         cudaFuncAttributeMaxDynamicSharedMemorySize, SMEM_TOTAL);
    fused_lin_lse_mish<<<CTAS, THREADS, SMEM_TOTAL>>>(x, W, out);
}